// round 3
// baseline (speedup 1.0000x reference)
#include <cuda_runtime.h>
#include <cuda_bf16.h>
#include <math.h>

// Shapes (fixed dataset):
//   x_all: [100000, 256] f32, n_id: [50000] i32, edge_index: [2, 300000] i32
//   W_sage: [256,256] f32, b_sage: [256] f32, W_cls: [3,256] f32, b_cls: [3] f32
//   out: [50000, 3] f32 (log_softmax)
#define NMAX 50000
#define FDIM 256
#define F4   64      // FDIM / 4
#define CCLS 3
#define CAP  96      // max degree capacity (Poisson(6): P(deg>=96) ~ 1e-60)

// Scratch (__device__ globals: allocation-free rule)
__device__ int   g_deg   [NMAX];          // in-degree (excl. self loop)
__device__ int   g_bucket[NMAX * CAP];    // per-dst list of x_all row ids (n_id[src])
__device__ float g_Wc    [CCLS * FDIM];   // fused weight
__device__ float g_bc    [CCLS];          // fused bias
__device__ float g_zero  [FDIM];          // all-zero row for branch-free tails

// ---------------------------------------------------------------------------
// Kernel 0: zero deg counters + zero row; block 0 additionally fuses the two
// linear layers:  Wc[c][k] = sum_h W_sage[k,h]*W_cls[c,h],
//                 bc[c]    = sum_h b_sage[h]*W_cls[c,h] + b_cls[c]
// ---------------------------------------------------------------------------
__global__ void k_prep_zero(const float* __restrict__ W_sage,
                            const float* __restrict__ b_sage,
                            const float* __restrict__ W_cls,
                            const float* __restrict__ b_cls, int N) {
    int gid = blockIdx.x * blockDim.x + threadIdx.x;
    if (gid < N) g_deg[gid] = 0;

    if (blockIdx.x != 0) return;
    int t = threadIdx.x;
    g_zero[t] = 0.0f;

    __shared__ float sWcls[CCLS][FDIM];
    #pragma unroll
    for (int c = 0; c < CCLS; c++) sWcls[c][t] = W_cls[c * FDIM + t];
    __syncthreads();

    float a0 = 0.f, a1 = 0.f, a2 = 0.f;
    const float* wrow = W_sage + t * FDIM;
    #pragma unroll 8
    for (int h = 0; h < FDIM; h++) {
        float w = wrow[h];
        a0 = fmaf(w, sWcls[0][h], a0);
        a1 = fmaf(w, sWcls[1][h], a1);
        a2 = fmaf(w, sWcls[2][h], a2);
    }
    g_Wc[0 * FDIM + t] = a0;
    g_Wc[1 * FDIM + t] = a1;
    g_Wc[2 * FDIM + t] = a2;

    if (t < CCLS) {
        float s = b_cls[t];
        for (int h = 0; h < FDIM; h++) s = fmaf(b_sage[h], sWcls[t][h], s);
        g_bc[t] = s;
    }
}

// ---------------------------------------------------------------------------
// Kernel 1: bucket scatter. Append n_id[src] to dst's bucket.
// ---------------------------------------------------------------------------
__global__ void k_scatter(const int* __restrict__ src,
                          const int* __restrict__ dst,
                          const int* __restrict__ n_id, int E) {
    int e = blockIdx.x * blockDim.x + threadIdx.x;
    if (e >= E) return;
    int d = __ldg(&dst[e]);
    int s = __ldg(&src[e]);
    int row = __ldg(&n_id[s]);               // pre-map to x_all row
    int pos = atomicAdd(&g_deg[d], 1);
    if (pos < CAP) g_bucket[d * CAP + pos] = row;
}

// ---------------------------------------------------------------------------
// Kernel 2: fused pull-aggregate + linear + log_softmax.
// One warp per node. Bucket indices fetched with ONE coalesced LDG (bkt[lane])
// and broadcast via shfl. Neighbor loop unrolled 4x with branch-free zero-row
// tail -> 8 float4 loads in flight per round.
// ---------------------------------------------------------------------------
__global__ void k_fused(const float4* __restrict__ x_all4,
                        const int* __restrict__ n_id,
                        float* __restrict__ out, int N) {
    __shared__ float sW[CCLS][FDIM];
    __shared__ float sb[CCLS];
    int t = threadIdx.x;
    for (int idx = t; idx < CCLS * FDIM; idx += blockDim.x)
        sW[idx >> 8][idx & 255] = g_Wc[idx];
    if (t < CCLS) sb[t] = g_bc[t];
    __syncthreads();

    int w    = (blockIdx.x * blockDim.x + t) >> 5;
    int lane = t & 31;
    if (w >= N) return;

    int deg = g_deg[w];
    const int* bkt = g_bucket + (long long)w * CAP;
    const float4* zp = reinterpret_cast<const float4*>(g_zero);

    // one coalesced load covers first 32 neighbor indices (garbage beyond deg OK)
    int idxv = __ldg(&bkt[lane]);

    // self loop
    int srow = __ldg(&n_id[w]);
    const float4* sp = x_all4 + (long long)srow * F4;
    float4 a0 = __ldg(&sp[lane]);
    float4 a1 = __ldg(&sp[lane + 32]);

    const unsigned full = 0xffffffffu;
    int d1 = deg < 32 ? deg : 32;
    for (int e = 0; e < d1; e += 4) {
        int r0 = __shfl_sync(full, idxv, e & 31);
        int r1 = __shfl_sync(full, idxv, (e + 1) & 31);
        int r2 = __shfl_sync(full, idxv, (e + 2) & 31);
        int r3 = __shfl_sync(full, idxv, (e + 3) & 31);
        const float4* p0 = x_all4 + (long long)r0 * F4;   // e < d1 guaranteed
        const float4* p1 = (e + 1 < d1) ? x_all4 + (long long)r1 * F4 : zp;
        const float4* p2 = (e + 2 < d1) ? x_all4 + (long long)r2 * F4 : zp;
        const float4* p3 = (e + 3 < d1) ? x_all4 + (long long)r3 * F4 : zp;
        float4 v00 = __ldg(&p0[lane]);      float4 v01 = __ldg(&p0[lane + 32]);
        float4 v10 = __ldg(&p1[lane]);      float4 v11 = __ldg(&p1[lane + 32]);
        float4 v20 = __ldg(&p2[lane]);      float4 v21 = __ldg(&p2[lane + 32]);
        float4 v30 = __ldg(&p3[lane]);      float4 v31 = __ldg(&p3[lane + 32]);
        // pairwise tree adds to shorten dependency chains
        float4 s0, s1;
        s0.x = (v00.x + v10.x) + (v20.x + v30.x);
        s0.y = (v00.y + v10.y) + (v20.y + v30.y);
        s0.z = (v00.z + v10.z) + (v20.z + v30.z);
        s0.w = (v00.w + v10.w) + (v20.w + v30.w);
        s1.x = (v01.x + v11.x) + (v21.x + v31.x);
        s1.y = (v01.y + v11.y) + (v21.y + v31.y);
        s1.z = (v01.z + v11.z) + (v21.z + v31.z);
        s1.w = (v01.w + v11.w) + (v21.w + v31.w);
        a0.x += s0.x; a0.y += s0.y; a0.z += s0.z; a0.w += s0.w;
        a1.x += s1.x; a1.y += s1.y; a1.z += s1.z; a1.w += s1.w;
    }
    // rare spill: degree > 32
    for (int e = 32; e < deg; e += 2) {
        int r0 = __ldg(&bkt[e]);
        int r1 = (e + 1 < deg) ? __ldg(&bkt[e + 1]) : -1;
        const float4* p0 = x_all4 + (long long)r0 * F4;
        const float4* p1 = (r1 >= 0) ? x_all4 + (long long)r1 * F4 : zp;
        float4 v00 = __ldg(&p0[lane]);      float4 v01 = __ldg(&p0[lane + 32]);
        float4 v10 = __ldg(&p1[lane]);      float4 v11 = __ldg(&p1[lane + 32]);
        a0.x += v00.x + v10.x; a0.y += v00.y + v10.y;
        a0.z += v00.z + v10.z; a0.w += v00.w + v10.w;
        a1.x += v01.x + v11.x; a1.y += v01.y + v11.y;
        a1.z += v01.z + v11.z; a1.w += v01.w + v11.w;
    }

    float inv = 1.0f / (float)(deg + 1);
    a0.x *= inv; a0.y *= inv; a0.z *= inv; a0.w *= inv;
    a1.x *= inv; a1.y *= inv; a1.z *= inv; a1.w *= inv;

    // 3 dot products against fused weight
    int k0 = lane * 4, k1 = (lane + 32) * 4;
    float s0, s1, s2;
    {
        float t0, t1, t2;
        t0 = fmaf(a0.x, sW[0][k0], fmaf(a0.y, sW[0][k0+1], fmaf(a0.z, sW[0][k0+2], a0.w * sW[0][k0+3])));
        t1 = fmaf(a0.x, sW[1][k0], fmaf(a0.y, sW[1][k0+1], fmaf(a0.z, sW[1][k0+2], a0.w * sW[1][k0+3])));
        t2 = fmaf(a0.x, sW[2][k0], fmaf(a0.y, sW[2][k0+1], fmaf(a0.z, sW[2][k0+2], a0.w * sW[2][k0+3])));
        s0 = fmaf(a1.x, sW[0][k1], fmaf(a1.y, sW[0][k1+1], fmaf(a1.z, sW[0][k1+2], fmaf(a1.w, sW[0][k1+3], t0))));
        s1 = fmaf(a1.x, sW[1][k1], fmaf(a1.y, sW[1][k1+1], fmaf(a1.z, sW[1][k1+2], fmaf(a1.w, sW[1][k1+3], t1))));
        s2 = fmaf(a1.x, sW[2][k1], fmaf(a1.y, sW[2][k1+1], fmaf(a1.z, sW[2][k1+2], fmaf(a1.w, sW[2][k1+3], t2))));
    }
    #pragma unroll
    for (int off = 16; off > 0; off >>= 1) {
        s0 += __shfl_down_sync(full, s0, off);
        s1 += __shfl_down_sync(full, s1, off);
        s2 += __shfl_down_sync(full, s2, off);
    }
    if (lane == 0) {
        s0 += sb[0]; s1 += sb[1]; s2 += sb[2];
        float m   = fmaxf(s0, fmaxf(s1, s2));
        float lse = m + logf(expf(s0 - m) + expf(s1 - m) + expf(s2 - m));
        out[w * 3 + 0] = s0 - lse;
        out[w * 3 + 1] = s1 - lse;
        out[w * 3 + 2] = s2 - lse;
    }
}

// ---------------------------------------------------------------------------
extern "C" void kernel_launch(void* const* d_in, const int* in_sizes, int n_in,
                              void* d_out, int out_size) {
    const float* x_all  = (const float*)d_in[0];
    const int*   n_id   = (const int*)  d_in[1];
    const int*   eidx   = (const int*)  d_in[2];
    const float* W_sage = (const float*)d_in[3];
    const float* b_sage = (const float*)d_in[4];
    const float* W_cls  = (const float*)d_in[5];
    const float* b_cls  = (const float*)d_in[6];
    float* out = (float*)d_out;

    int N = in_sizes[1];          // 50000
    int E = in_sizes[2] / 2;      // 300000
    const int* src = eidx;        // edge_index[0, :]
    const int* dst = eidx + E;    // edge_index[1, :]

    k_prep_zero<<<(N + 255) / 256, 256>>>(W_sage, b_sage, W_cls, b_cls, N);
    k_scatter<<<(E + 255) / 256, 256>>>(src, dst, n_id, E);

    long long fth = (long long)N * 32;
    k_fused<<<(int)((fth + 255) / 256), 256>>>(
        reinterpret_cast<const float4*>(x_all), n_id, out, N);
}

// round 4
// speedup vs baseline: 1.8356x; 1.8356x over previous
#include <cuda_runtime.h>
#include <cuda_bf16.h>
#include <math.h>

// Shapes (fixed dataset):
//   x_all: [100000, 256] f32, n_id: [50000] i32, edge_index: [2, 300000] i32
//   W_sage: [256,256] f32, b_sage: [256] f32, W_cls: [3,256] f32, b_cls: [3] f32
//   out: [50000, 3] f32 (log_softmax)
#define NMAX 50000
#define FDIM 256
#define F4   64      // FDIM / 4
#define CCLS 3
#define CAP  96      // max degree capacity (Poisson(6): P(deg>=96) ~ 1e-60)

// Scratch (__device__ globals: allocation-free rule)
__device__ int   g_deg   [NMAX];          // in-degree (excl. self loop)
__device__ int   g_bucket[NMAX * CAP];    // per-dst list of x_all row ids (n_id[src])
__device__ float g_Wc    [CCLS * FDIM];   // fused weight
__device__ float g_bc    [CCLS];          // fused bias
__device__ float g_zero  [FDIM];          // all-zero row for branch-free tails

// ---------------------------------------------------------------------------
// Kernel 0: init + PARALLEL weight fusion.
//   - thread gid < N      : g_deg[gid] = 0
//   - thread gid < FDIM   : g_zero[gid] = 0
//   - warp ww < 768       : Wc[c][k] = dot(W_sage[k,:], W_cls[c,:])  (warp-reduced)
//   - warp ww in [768,771): bc[c] = dot(b_sage, W_cls[c,:]) + b_cls[c]
// 768+3 warps spread across the whole grid -> all SMs busy, ~2us.
// ---------------------------------------------------------------------------
__global__ void k_init(const float* __restrict__ W_sage,
                       const float* __restrict__ b_sage,
                       const float* __restrict__ W_cls,
                       const float* __restrict__ b_cls, int N) {
    int gid = blockIdx.x * blockDim.x + threadIdx.x;
    if (gid < N)    g_deg[gid]  = 0;
    if (gid < FDIM) g_zero[gid] = 0.0f;

    int ww   = gid >> 5;
    int lane = gid & 31;
    const unsigned full = 0xffffffffu;

    if (ww < CCLS * FDIM) {
        int c = ww >> 8;          // ww / FDIM
        int k = ww & 255;         // ww % FDIM
        const float4* wrow = reinterpret_cast<const float4*>(W_sage + k * FDIM);
        const float4* crow = reinterpret_cast<const float4*>(W_cls  + c * FDIM);
        float4 a0 = __ldg(&wrow[lane]);      float4 b0 = __ldg(&crow[lane]);
        float4 a1 = __ldg(&wrow[lane + 32]); float4 b1 = __ldg(&crow[lane + 32]);
        float s = fmaf(a0.x, b0.x, fmaf(a0.y, b0.y, fmaf(a0.z, b0.z, a0.w * b0.w)))
                + fmaf(a1.x, b1.x, fmaf(a1.y, b1.y, fmaf(a1.z, b1.z, a1.w * b1.w)));
        #pragma unroll
        for (int off = 16; off > 0; off >>= 1)
            s += __shfl_down_sync(full, s, off);
        if (lane == 0) g_Wc[c * FDIM + k] = s;
    } else if (ww < CCLS * FDIM + CCLS) {
        int c = ww - CCLS * FDIM;
        const float4* brow = reinterpret_cast<const float4*>(b_sage);
        const float4* crow = reinterpret_cast<const float4*>(W_cls + c * FDIM);
        float4 a0 = __ldg(&brow[lane]);      float4 b0 = __ldg(&crow[lane]);
        float4 a1 = __ldg(&brow[lane + 32]); float4 b1 = __ldg(&crow[lane + 32]);
        float s = fmaf(a0.x, b0.x, fmaf(a0.y, b0.y, fmaf(a0.z, b0.z, a0.w * b0.w)))
                + fmaf(a1.x, b1.x, fmaf(a1.y, b1.y, fmaf(a1.z, b1.z, a1.w * b1.w)));
        #pragma unroll
        for (int off = 16; off > 0; off >>= 1)
            s += __shfl_down_sync(full, s, off);
        if (lane == 0) g_bc[c] = s + __ldg(&b_cls[c]);
    }
}

// ---------------------------------------------------------------------------
// Kernel 1: bucket scatter. Append n_id[src] to dst's bucket.
// ---------------------------------------------------------------------------
__global__ void k_scatter(const int* __restrict__ src,
                          const int* __restrict__ dst,
                          const int* __restrict__ n_id, int E) {
    int e = blockIdx.x * blockDim.x + threadIdx.x;
    if (e >= E) return;
    int d = __ldg(&dst[e]);
    int s = __ldg(&src[e]);
    int row = __ldg(&n_id[s]);               // pre-map to x_all row
    int pos = atomicAdd(&g_deg[d], 1);
    if (pos < CAP) g_bucket[d * CAP + pos] = row;
}

// ---------------------------------------------------------------------------
// Kernel 2: fused pull-aggregate + linear + log_softmax.
// One warp per node. Bucket indices fetched with ONE coalesced LDG (bkt[lane])
// and broadcast via shfl. Neighbor loop unrolled 4x with branch-free zero-row
// tail -> 8 float4 loads in flight per round.
// ---------------------------------------------------------------------------
__global__ void k_fused(const float4* __restrict__ x_all4,
                        const int* __restrict__ n_id,
                        float* __restrict__ out, int N) {
    __shared__ float sW[CCLS][FDIM];
    __shared__ float sb[CCLS];
    int t = threadIdx.x;
    for (int idx = t; idx < CCLS * FDIM; idx += blockDim.x)
        sW[idx >> 8][idx & 255] = g_Wc[idx];
    if (t < CCLS) sb[t] = g_bc[t];
    __syncthreads();

    int w    = (blockIdx.x * blockDim.x + t) >> 5;
    int lane = t & 31;
    if (w >= N) return;

    int deg = g_deg[w];
    const int* bkt = g_bucket + (long long)w * CAP;
    const float4* zp = reinterpret_cast<const float4*>(g_zero);

    // one coalesced load covers first 32 neighbor indices (garbage beyond deg OK)
    int idxv = __ldg(&bkt[lane]);

    // self loop
    int srow = __ldg(&n_id[w]);
    const float4* sp = x_all4 + (long long)srow * F4;
    float4 a0 = __ldg(&sp[lane]);
    float4 a1 = __ldg(&sp[lane + 32]);

    const unsigned full = 0xffffffffu;
    int d1 = deg < 32 ? deg : 32;
    for (int e = 0; e < d1; e += 4) {
        int r0 = __shfl_sync(full, idxv, e & 31);
        int r1 = __shfl_sync(full, idxv, (e + 1) & 31);
        int r2 = __shfl_sync(full, idxv, (e + 2) & 31);
        int r3 = __shfl_sync(full, idxv, (e + 3) & 31);
        const float4* p0 = x_all4 + (long long)r0 * F4;   // e < d1 guaranteed
        const float4* p1 = (e + 1 < d1) ? x_all4 + (long long)r1 * F4 : zp;
        const float4* p2 = (e + 2 < d1) ? x_all4 + (long long)r2 * F4 : zp;
        const float4* p3 = (e + 3 < d1) ? x_all4 + (long long)r3 * F4 : zp;
        float4 v00 = __ldg(&p0[lane]);      float4 v01 = __ldg(&p0[lane + 32]);
        float4 v10 = __ldg(&p1[lane]);      float4 v11 = __ldg(&p1[lane + 32]);
        float4 v20 = __ldg(&p2[lane]);      float4 v21 = __ldg(&p2[lane + 32]);
        float4 v30 = __ldg(&p3[lane]);      float4 v31 = __ldg(&p3[lane + 32]);
        // pairwise tree adds to shorten dependency chains
        float4 s0, s1;
        s0.x = (v00.x + v10.x) + (v20.x + v30.x);
        s0.y = (v00.y + v10.y) + (v20.y + v30.y);
        s0.z = (v00.z + v10.z) + (v20.z + v30.z);
        s0.w = (v00.w + v10.w) + (v20.w + v30.w);
        s1.x = (v01.x + v11.x) + (v21.x + v31.x);
        s1.y = (v01.y + v11.y) + (v21.y + v31.y);
        s1.z = (v01.z + v11.z) + (v21.z + v31.z);
        s1.w = (v01.w + v11.w) + (v21.w + v31.w);
        a0.x += s0.x; a0.y += s0.y; a0.z += s0.z; a0.w += s0.w;
        a1.x += s1.x; a1.y += s1.y; a1.z += s1.z; a1.w += s1.w;
    }
    // rare spill: degree > 32
    for (int e = 32; e < deg; e += 2) {
        int r0 = __ldg(&bkt[e]);
        int r1 = (e + 1 < deg) ? __ldg(&bkt[e + 1]) : -1;
        const float4* p0 = x_all4 + (long long)r0 * F4;
        const float4* p1 = (r1 >= 0) ? x_all4 + (long long)r1 * F4 : zp;
        float4 v00 = __ldg(&p0[lane]);      float4 v01 = __ldg(&p0[lane + 32]);
        float4 v10 = __ldg(&p1[lane]);      float4 v11 = __ldg(&p1[lane + 32]);
        a0.x += v00.x + v10.x; a0.y += v00.y + v10.y;
        a0.z += v00.z + v10.z; a0.w += v00.w + v10.w;
        a1.x += v01.x + v11.x; a1.y += v01.y + v11.y;
        a1.z += v01.z + v11.z; a1.w += v01.w + v11.w;
    }

    float inv = 1.0f / (float)(deg + 1);
    a0.x *= inv; a0.y *= inv; a0.z *= inv; a0.w *= inv;
    a1.x *= inv; a1.y *= inv; a1.z *= inv; a1.w *= inv;

    // 3 dot products against fused weight
    int k0 = lane * 4, k1 = (lane + 32) * 4;
    float s0, s1, s2;
    {
        float t0, t1, t2;
        t0 = fmaf(a0.x, sW[0][k0], fmaf(a0.y, sW[0][k0+1], fmaf(a0.z, sW[0][k0+2], a0.w * sW[0][k0+3])));
        t1 = fmaf(a0.x, sW[1][k0], fmaf(a0.y, sW[1][k0+1], fmaf(a0.z, sW[1][k0+2], a0.w * sW[1][k0+3])));
        t2 = fmaf(a0.x, sW[2][k0], fmaf(a0.y, sW[2][k0+1], fmaf(a0.z, sW[2][k0+2], a0.w * sW[2][k0+3])));
        s0 = fmaf(a1.x, sW[0][k1], fmaf(a1.y, sW[0][k1+1], fmaf(a1.z, sW[0][k1+2], fmaf(a1.w, sW[0][k1+3], t0))));
        s1 = fmaf(a1.x, sW[1][k1], fmaf(a1.y, sW[1][k1+1], fmaf(a1.z, sW[1][k1+2], fmaf(a1.w, sW[1][k1+3], t1))));
        s2 = fmaf(a1.x, sW[2][k1], fmaf(a1.y, sW[2][k1+1], fmaf(a1.z, sW[2][k1+2], fmaf(a1.w, sW[2][k1+3], t2))));
    }
    #pragma unroll
    for (int off = 16; off > 0; off >>= 1) {
        s0 += __shfl_down_sync(full, s0, off);
        s1 += __shfl_down_sync(full, s1, off);
        s2 += __shfl_down_sync(full, s2, off);
    }
    if (lane == 0) {
        s0 += sb[0]; s1 += sb[1]; s2 += sb[2];
        float m   = fmaxf(s0, fmaxf(s1, s2));
        float lse = m + logf(expf(s0 - m) + expf(s1 - m) + expf(s2 - m));
        out[w * 3 + 0] = s0 - lse;
        out[w * 3 + 1] = s1 - lse;
        out[w * 3 + 2] = s2 - lse;
    }
}

// ---------------------------------------------------------------------------
extern "C" void kernel_launch(void* const* d_in, const int* in_sizes, int n_in,
                              void* d_out, int out_size) {
    const float* x_all  = (const float*)d_in[0];
    const int*   n_id   = (const int*)  d_in[1];
    const int*   eidx   = (const int*)  d_in[2];
    const float* W_sage = (const float*)d_in[3];
    const float* b_sage = (const float*)d_in[4];
    const float* W_cls  = (const float*)d_in[5];
    const float* b_cls  = (const float*)d_in[6];
    float* out = (float*)d_out;

    int N = in_sizes[1];          // 50000
    int E = in_sizes[2] / 2;      // 300000
    const int* src = eidx;        // edge_index[0, :]
    const int* dst = eidx + E;    // edge_index[1, :]

    // enough threads to cover N deg-zeros AND (768+3) fusion warps
    int init_threads = N;
    int warps_needed = (CCLS * FDIM + CCLS) * 32;
    if (warps_needed > init_threads) init_threads = warps_needed;
    k_init<<<(init_threads + 255) / 256, 256>>>(W_sage, b_sage, W_cls, b_cls, N);

    k_scatter<<<(E + 255) / 256, 256>>>(src, dst, n_id, E);

    long long fth = (long long)N * 32;
    k_fused<<<(int)((fth + 255) / 256), 256>>>(
        reinterpret_cast<const float4*>(x_all), n_id, out, N);
}

// round 5
// speedup vs baseline: 3.3316x; 1.8151x over previous
#include <cuda_runtime.h>
#include <cuda_bf16.h>
#include <math.h>

// Shapes (fixed dataset):
//   x_all: [100000, 256] f32, n_id: [50000] i32, edge_index: [2, 300000] i32
//   W_sage: [256,256] f32, b_sage: [256] f32, W_cls: [3,256] f32, b_cls: [3] f32
//   out: [50000, 3] f32 (log_softmax)
//
// Algebra: out = log_softmax( mean_{j in N(i)+self}( x[j] ) @ Wc + bc )
//        = log_softmax( mean_{j}( x[j] @ Wc ) + bc )            (linearity!)
// where Wc[k][c] = sum_h W_sage[k,h] W_cls[c,h],  bc[c] = b_sage@W_cls[c] + b_cls[c].
// So: project each node row to 3 floats ONCE, then aggregate 3-vectors over edges.
#define NMAX 50000
#define FDIM 256
#define F4   64      // FDIM / 4
#define CCLS 3

// Scratch (__device__ globals: allocation-free rule)
__device__ float  g_Wc [CCLS * FDIM];   // fused weight
__device__ float  g_bc [CCLS];          // fused bias
__device__ float4 g_z  [NMAX];          // per-node projected scores {s0,s1,s2, 1.0}
__device__ float4 g_acc[NMAX];          // accumulated {sum0,sum1,sum2, cnt}

// ---------------------------------------------------------------------------
// Kernel 0: parallel weight fusion. One warp per output element.
// ---------------------------------------------------------------------------
__global__ void k_init(const float* __restrict__ W_sage,
                       const float* __restrict__ b_sage,
                       const float* __restrict__ W_cls,
                       const float* __restrict__ b_cls) {
    int gid  = blockIdx.x * blockDim.x + threadIdx.x;
    int ww   = gid >> 5;
    int lane = gid & 31;
    const unsigned full = 0xffffffffu;

    if (ww < CCLS * FDIM) {
        int c = ww >> 8;          // ww / FDIM
        int k = ww & 255;         // ww % FDIM
        const float4* wrow = reinterpret_cast<const float4*>(W_sage + k * FDIM);
        const float4* crow = reinterpret_cast<const float4*>(W_cls  + c * FDIM);
        float4 a0 = __ldg(&wrow[lane]);      float4 b0 = __ldg(&crow[lane]);
        float4 a1 = __ldg(&wrow[lane + 32]); float4 b1 = __ldg(&crow[lane + 32]);
        float s = fmaf(a0.x, b0.x, fmaf(a0.y, b0.y, fmaf(a0.z, b0.z, a0.w * b0.w)))
                + fmaf(a1.x, b1.x, fmaf(a1.y, b1.y, fmaf(a1.z, b1.z, a1.w * b1.w)));
        #pragma unroll
        for (int off = 16; off > 0; off >>= 1)
            s += __shfl_down_sync(full, s, off);
        if (lane == 0) g_Wc[c * FDIM + k] = s;
    } else if (ww < CCLS * FDIM + CCLS) {
        int c = ww - CCLS * FDIM;
        const float4* brow = reinterpret_cast<const float4*>(b_sage);
        const float4* crow = reinterpret_cast<const float4*>(W_cls + c * FDIM);
        float4 a0 = __ldg(&brow[lane]);      float4 b0 = __ldg(&crow[lane]);
        float4 a1 = __ldg(&brow[lane + 32]); float4 b1 = __ldg(&crow[lane + 32]);
        float s = fmaf(a0.x, b0.x, fmaf(a0.y, b0.y, fmaf(a0.z, b0.z, a0.w * b0.w)))
                + fmaf(a1.x, b1.x, fmaf(a1.y, b1.y, fmaf(a1.z, b1.z, a1.w * b1.w)));
        #pragma unroll
        for (int off = 16; off > 0; off >>= 1)
            s += __shfl_down_sync(full, s, off);
        if (lane == 0) g_bc[c] = s + __ldg(&b_cls[c]);
    }
}

// ---------------------------------------------------------------------------
// Kernel 1: project. One warp per node: z[i] = x_all[n_id[i]] @ Wc, .w = 1.
// Also seeds acc[i] = z[i] (the self loop + count).
// ---------------------------------------------------------------------------
__global__ void k_z(const float4* __restrict__ x_all4,
                    const int* __restrict__ n_id, int N) {
    __shared__ float sW[CCLS][FDIM];
    int t = threadIdx.x;
    for (int idx = t; idx < CCLS * FDIM; idx += blockDim.x)
        sW[idx >> 8][idx & 255] = g_Wc[idx];
    __syncthreads();

    int w    = (blockIdx.x * blockDim.x + t) >> 5;
    int lane = t & 31;
    if (w >= N) return;

    int row = __ldg(&n_id[w]);
    const float4* xp = x_all4 + (long long)row * F4;
    float4 a0 = __ldg(&xp[lane]);
    float4 a1 = __ldg(&xp[lane + 32]);

    int k0 = lane * 4, k1 = (lane + 32) * 4;
    float s0, s1, s2;
    {
        float t0, t1, t2;
        t0 = fmaf(a0.x, sW[0][k0], fmaf(a0.y, sW[0][k0+1], fmaf(a0.z, sW[0][k0+2], a0.w * sW[0][k0+3])));
        t1 = fmaf(a0.x, sW[1][k0], fmaf(a0.y, sW[1][k0+1], fmaf(a0.z, sW[1][k0+2], a0.w * sW[1][k0+3])));
        t2 = fmaf(a0.x, sW[2][k0], fmaf(a0.y, sW[2][k0+1], fmaf(a0.z, sW[2][k0+2], a0.w * sW[2][k0+3])));
        s0 = fmaf(a1.x, sW[0][k1], fmaf(a1.y, sW[0][k1+1], fmaf(a1.z, sW[0][k1+2], fmaf(a1.w, sW[0][k1+3], t0))));
        s1 = fmaf(a1.x, sW[1][k1], fmaf(a1.y, sW[1][k1+1], fmaf(a1.z, sW[1][k1+2], fmaf(a1.w, sW[1][k1+3], t1))));
        s2 = fmaf(a1.x, sW[2][k1], fmaf(a1.y, sW[2][k1+1], fmaf(a1.z, sW[2][k1+2], fmaf(a1.w, sW[2][k1+3], t2))));
    }
    const unsigned full = 0xffffffffu;
    #pragma unroll
    for (int off = 16; off > 0; off >>= 1) {
        s0 += __shfl_down_sync(full, s0, off);
        s1 += __shfl_down_sync(full, s1, off);
        s2 += __shfl_down_sync(full, s2, off);
    }
    if (lane == 0) {
        float4 zv = make_float4(s0, s1, s2, 1.0f);
        g_z[w]   = zv;   // projection
        g_acc[w] = zv;   // self-loop seed (count starts at 1)
    }
}

// ---------------------------------------------------------------------------
// Kernel 2: edge aggregation over 3-vectors. One thread per edge:
//   acc[dst] += z[src]   (the .w component counts neighbors)
// z is 800KB -> L2-resident. Vectorized no-return reduction.
// ---------------------------------------------------------------------------
__global__ void k_edge(const int* __restrict__ src,
                       const int* __restrict__ dst, int E) {
    int e = blockIdx.x * blockDim.x + threadIdx.x;
    if (e >= E) return;
    int s = __ldg(&src[e]);
    int d = __ldg(&dst[e]);
    float4 v = __ldg(&g_z[s]);
    asm volatile("red.global.add.v4.f32 [%0], {%1, %2, %3, %4};"
                 :: "l"(&g_acc[d]), "f"(v.x), "f"(v.y), "f"(v.z), "f"(v.w)
                 : "memory");
}

// ---------------------------------------------------------------------------
// Kernel 3: finalize. One thread per node: mean, +bc, log_softmax.
// ---------------------------------------------------------------------------
__global__ void k_final(float* __restrict__ out, int N) {
    int i = blockIdx.x * blockDim.x + threadIdx.x;
    if (i >= N) return;
    float4 a = g_acc[i];
    float inv = 1.0f / a.w;
    float s0 = fmaf(a.x, inv, g_bc[0]);
    float s1 = fmaf(a.y, inv, g_bc[1]);
    float s2 = fmaf(a.z, inv, g_bc[2]);
    float m   = fmaxf(s0, fmaxf(s1, s2));
    float lse = m + logf(expf(s0 - m) + expf(s1 - m) + expf(s2 - m));
    out[i * 3 + 0] = s0 - lse;
    out[i * 3 + 1] = s1 - lse;
    out[i * 3 + 2] = s2 - lse;
}

// ---------------------------------------------------------------------------
extern "C" void kernel_launch(void* const* d_in, const int* in_sizes, int n_in,
                              void* d_out, int out_size) {
    const float* x_all  = (const float*)d_in[0];
    const int*   n_id   = (const int*)  d_in[1];
    const int*   eidx   = (const int*)  d_in[2];
    const float* W_sage = (const float*)d_in[3];
    const float* b_sage = (const float*)d_in[4];
    const float* W_cls  = (const float*)d_in[5];
    const float* b_cls  = (const float*)d_in[6];
    float* out = (float*)d_out;

    int N = in_sizes[1];          // 50000
    int E = in_sizes[2] / 2;      // 300000
    const int* src = eidx;        // edge_index[0, :]
    const int* dst = eidx + E;    // edge_index[1, :]

    int init_threads = (CCLS * FDIM + CCLS) * 32;
    k_init<<<(init_threads + 255) / 256, 256>>>(W_sage, b_sage, W_cls, b_cls);

    long long zth = (long long)N * 32;
    k_z<<<(int)((zth + 255) / 256), 256>>>(
        reinterpret_cast<const float4*>(x_all), n_id, N);

    k_edge<<<(E + 255) / 256, 256>>>(src, dst, E);

    k_final<<<(N + 255) / 256, 256>>>(out, N);
}